// round 16
// baseline (speedup 1.0000x reference)
#include <cuda_runtime.h>
#include <cuda_bf16.h>
#include <math.h>
#include <stdint.h>

// Problem constants
#define BB 8
#define SS 4096
#define DD 256
#define GG 3
#define NORD 2
#define NF 8192          // FFT length = 2*S
#define LOG2NF 13

// padded smem index for FFT
#define FIDX(i) ((i) + ((i) >> 4))
#define SA_PAD 8704
#define TW_PAD 2176

// GEMM stage layout (dynamic smem), per stage 16896 B
#define STG 16896
#define GEMM_SMEM (3 * STG)      // 50688

// ---------------- device scratch (static, no allocation) ----------------
__device__ float  g_minpos[BB];
__device__ float  g_theta[128];
__device__ float2 g_tw[NF/4];
__device__ __nv_bfloat16 g_embh[BB * SS * 256];
__device__ __nv_bfloat16 g_embl[BB * SS * 256];
__device__ __nv_bfloat16 g_th[BB * SS * 256];
__device__ __nv_bfloat16 g_tl[BB * SS * 256];
__device__ __nv_bfloat16 g_vTh[BB * SS * 256];
__device__ __nv_bfloat16 g_vTl[BB * SS * 256];
// K-pair-packed bf16 weights: u32 = bf16(k even) | bf16(k odd)<<16, layout [K/2][N]
__device__ uint32_t g_Wch[384 * 768];
__device__ uint32_t g_Wcl[384 * 768];
__device__ uint32_t g_W1h[128 * 256];
__device__ uint32_t g_W1l[128 * 256];
__device__ uint32_t g_W2h[128 * 512];
__device__ uint32_t g_W2l[128 * 512];
__device__ uint32_t g_Woh[128 * 256];
__device__ uint32_t g_Wol[128 * 256];
// f32 intermediates
__device__ float  g_z[BB * GG * DD * SS];          // [b][g][d][s]
__device__ float  g_h1[BB * SS * DD];
__device__ float  g_hh[BB * SS * 2 * DD];
__device__ float  g_h[NORD * BB * DD * SS];        // [n][b][d][s]
__device__ float  g_v[BB * DD * SS];               // [b][d][s]

// ---------------- helpers ----------------
__device__ __forceinline__ uint32_t sptr(const void* p) {
    return (uint32_t)__cvta_generic_to_shared(p);
}
__device__ __forceinline__ void cpa16(uint32_t dst, const void* src, int sz) {
    asm volatile("cp.async.ca.shared.global [%0], [%1], 16, %2;\n"
                 :: "r"(dst), "l"(src), "r"(sz));
}
__device__ __forceinline__ void cpa_commit() {
    asm volatile("cp.async.commit_group;\n" ::: "memory");
}
__device__ __forceinline__ void cpa_wait1() {
    asm volatile("cp.async.wait_group 1;\n" ::: "memory");
}
__device__ __forceinline__ void cpa_wait0() {
    asm volatile("cp.async.wait_group 0;\n" ::: "memory");
}
__device__ __forceinline__ uint32_t pk2(__nv_bfloat16 a, __nv_bfloat16 b) {
    return (uint32_t)__bfloat16_as_ushort(a) | ((uint32_t)__bfloat16_as_ushort(b) << 16);
}
__device__ __forceinline__ void mma16(float c[4], const uint32_t a[4], const uint32_t b[2]) {
    asm volatile(
        "mma.sync.aligned.m16n8k16.row.col.f32.bf16.bf16.f32 "
        "{%0,%1,%2,%3}, {%4,%5,%6,%7}, {%8,%9}, {%0,%1,%2,%3};\n"
        : "+f"(c[0]), "+f"(c[1]), "+f"(c[2]), "+f"(c[3])
        : "r"(a[0]), "r"(a[1]), "r"(a[2]), "r"(a[3]), "r"(b[0]), "r"(b[1]));
}
__device__ __forceinline__ void ldsm4(uint32_t r[4], uint32_t addr) {
    asm volatile("ldmatrix.sync.aligned.m8n8.x4.shared.b16 {%0,%1,%2,%3}, [%4];"
                 : "=r"(r[0]), "=r"(r[1]), "=r"(r[2]), "=r"(r[3]) : "r"(addr));
}
__device__ __forceinline__ float2 cmul(float2 a, float2 b) {
    return make_float2(a.x * b.x - a.y * b.y, a.x * b.y + a.y * b.x);
}
__device__ __forceinline__ float2 cmulc(float2 a, float2 w) {
    return make_float2(a.x * w.x + a.y * w.y, a.y * w.x - a.x * w.y);
}
__device__ __forceinline__ float2 cadd(float2 a, float2 b) { return make_float2(a.x + b.x, a.y + b.y); }
__device__ __forceinline__ float2 csub(float2 a, float2 b) { return make_float2(a.x - b.x, a.y - b.y); }

// radix-8 DIF group (3 fused radix-2 stages), bit-reversal-order preserving
__device__ __forceinline__ void r8_fwd(float2* arr, const int idx[8],
                                       const float2 W1e[4], float2 w2, float2 w2i, float2 w4)
{
    float2 a[8];
    #pragma unroll
    for (int e = 0; e < 8; e++) a[e] = arr[idx[e]];
    float2 sA[8];
    #pragma unroll
    for (int e = 0; e < 4; e++) {
        sA[e]     = cadd(a[e], a[e + 4]);
        sA[e + 4] = cmul(csub(a[e], a[e + 4]), W1e[e]);
    }
    float2 sB[8];
    #pragma unroll
    for (int h = 0; h < 8; h += 4) {
        sB[h]     = cadd(sA[h], sA[h + 2]);
        sB[h + 2] = cmul(csub(sA[h], sA[h + 2]), w2);
        sB[h + 1] = cadd(sA[h + 1], sA[h + 3]);
        sB[h + 3] = cmul(csub(sA[h + 1], sA[h + 3]), w2i);
    }
    #pragma unroll
    for (int h = 0; h < 8; h += 2) {
        arr[idx[h]]     = cadd(sB[h], sB[h + 1]);
        arr[idx[h + 1]] = cmul(csub(sB[h], sB[h + 1]), w4);
    }
}

// ---------------- split precompute kernels ----------------
__global__ void emb_split_kernel(const float* __restrict__ emb) {
    int i = blockIdx.x * 256 + threadIdx.x;
    float v = emb[i];
    __nv_bfloat16 h = __float2bfloat16(v);
    g_embh[i] = h;
    g_embl[i] = __float2bfloat16(v - __bfloat162float(h));
}

__global__ void wsplit_kernel(const float* __restrict__ W1, const float* __restrict__ W2,
                              const float* __restrict__ Wout) {
    int idx = blockIdx.x * 256 + threadIdx.x;
    const float* src; uint32_t *dh, *dl; int LDN, loc;
    if (idx < 32768)       { src = W1;   dh = g_W1h; dl = g_W1l; LDN = 256; loc = idx; }
    else if (idx < 98304)  { src = W2;   dh = g_W2h; dl = g_W2l; LDN = 512; loc = idx - 32768; }
    else                   { src = Wout; dh = g_Woh; dl = g_Wol; LDN = 256; loc = idx - 98304; }
    int kp = loc / LDN, n = loc % LDN;
    float v0 = src[(size_t)(2 * kp) * LDN + n];
    float v1 = src[(size_t)(2 * kp + 1) * LDN + n];
    __nv_bfloat16 h0 = __float2bfloat16(v0), h1 = __float2bfloat16(v1);
    dh[loc] = pk2(h0, h1);
    dl[loc] = pk2(__float2bfloat16(v0 - __bfloat162float(h0)),
                  __float2bfloat16(v1 - __bfloat162float(h1)));
}

// ---------------- init kernels ----------------
__global__ void tw_init_kernel() {
    int k = blockIdx.x * blockDim.x + threadIdx.x;
    if (k < NF/4) {
        double a = -2.0 * 3.14159265358979323846 * (double)k / (double)NF;
        double s, c;
        sincos(a, &s, &c);
        g_tw[k] = make_float2((float)c, (float)s);
    }
    if (k < 128) {
        float frac = (float)k * (1.0f / 128.0f);
        g_theta[k] = 1.0f / powf(10000.0f, frac);
    }
}

__global__ void minpos_kernel(const int* __restrict__ pos) {
    int b = blockIdx.x;
    int t = threadIdx.x;
    int local = 0x7fffffff;
    for (int s = t; s < SS; s += blockDim.x) {
        int p = pos[b * SS + s];
        if (p != -1) local = min(local, p);
    }
    for (int o = 16; o > 0; o >>= 1) local = min(local, __shfl_down_sync(0xffffffffu, local, o));
    __shared__ int wmin[8];
    if ((t & 31) == 0) wmin[t >> 5] = local;
    __syncthreads();
    if (t == 0) {
        int m = wmin[0];
        for (int i = 1; i < (int)(blockDim.x >> 5); i++) m = min(m, wmin[i]);
        g_minpos[b] = (float)m;
    }
}

// ---------------- SIMT gemm for Wc precompute ----------------
#define GEMM_CORE()                                                        \
    __syncthreads();                                                       \
    _Pragma("unroll")                                                      \
    for (int kk = 0; kk < 16; kk++) {                                      \
        float4 af = *(const float4*)&As[kk][ty * 4];                       \
        float4 bf = *(const float4*)&Bs[kk][tx * 4];                       \
        float ar[4] = {af.x, af.y, af.z, af.w};                            \
        float br[4] = {bf.x, bf.y, bf.z, bf.w};                            \
        _Pragma("unroll")                                                  \
        for (int i = 0; i < 4; i++)                                        \
            _Pragma("unroll")                                              \
            for (int j = 0; j < 4; j++) acc[i][j] += ar[i] * br[j];        \
    }                                                                      \
    __syncthreads();

__global__ void wc_gemm(const float* __restrict__ Wproj, const float* __restrict__ convw) {
    __shared__ __align__(16) float As[16][64];
    __shared__ __align__(16) float Bs[16][64];
    int t = threadIdx.x;
    int tx = t & 15, ty = t >> 4;
    int n0 = blockIdx.x * 64;         // c
    int m0 = blockIdx.y * 64;         // d
    int tap = blockIdx.z;
    int g = n0 >> 8;
    int am = t >> 2, akq = t & 3;
    int bk = t >> 4, bnq = t & 15;
    float acc[4][4] = {};
    for (int k0 = 0; k0 < 256; k0 += 16) {
        float4 av = *(const float4*)(Wproj + (size_t)(m0 + am) * 768 + g * 256 + k0 + akq * 4);
        As[akq * 4 + 0][am] = av.x;
        As[akq * 4 + 1][am] = av.y;
        As[akq * 4 + 2][am] = av.z;
        As[akq * 4 + 3][am] = av.w;
        int i = k0 + bk;
        int c = n0 + bnq * 4;
        #pragma unroll
        for (int e = 0; e < 4; e++)
            Bs[bk][bnq * 4 + e] = convw[(size_t)(c + e) * 768 + i * 3 + tap];
        GEMM_CORE()
    }
    #pragma unroll
    for (int i = 0; i < 4; i += 2) {
        int kglob = tap * 256 + m0 + ty * 4 + i;
        size_t kpg = (size_t)(kglob >> 1);
        #pragma unroll
        for (int j = 0; j < 4; j++) {
            float v0 = acc[i][j], v1 = acc[i + 1][j];
            __nv_bfloat16 h0 = __float2bfloat16(v0), h1 = __float2bfloat16(v1);
            int cidx = n0 + tx * 4 + j;
            g_Wch[kpg * 768 + cidx] = pk2(h0, h1);
            g_Wcl[kpg * 768 + cidx] = pk2(__float2bfloat16(v0 - __bfloat162float(h0)),
                                          __float2bfloat16(v1 - __bfloat162float(h1)));
        }
    }
}

// ---------------- rope (writes bf16 split) ----------------
__global__ void rope_kernel(const float* __restrict__ emb, const int* __restrict__ pos) {
    int row = blockIdx.x;
    int i = threadIdx.x;
    int b = row >> 12;
    float2 xv = *(const float2*)(emb + (size_t)row * 256 + 2 * i);
    float theta = g_theta[i];
    int p = pos[row];
    float adj = (p == -1) ? -1.0f : ((float)p - g_minpos[b]);
    float ang = adj * theta;
    float sn, cs;
    sincosf(ang, &sn, &cs);
    float rx = xv.x * cs - xv.y * sn;
    float ry = xv.x * sn + xv.y * cs;
    __nv_bfloat16 hx = __float2bfloat16(rx), hy = __float2bfloat16(ry);
    size_t o = (size_t)row * 256 + 2 * i;
    *(uint32_t*)(g_th + o) = pk2(hx, hy);
    *(uint32_t*)(g_tl + o) = pk2(__float2bfloat16(rx - __bfloat162float(hx)),
                                 __float2bfloat16(ry - __bfloat162float(hy)));
}

// One BK=16 slab, warp tile 32x32, bf16x3 (hi*hi + hi*lo + lo*hi)
__device__ __forceinline__ void compute_slab_bf(
    char* sb, int wm, int wn, int g, int tig, int lane, float acc[2][4][4])
{
    uint32_t a_hi = sptr(sb);
    uint32_t a_lo = a_hi + 6144;
    const uint32_t* Bh = (const uint32_t*)(sb + 12288);
    const uint32_t* Bl = (const uint32_t*)(sb + 14592);

    uint32_t bh[4][2], bl[4][2];
    #pragma unroll
    for (int nt = 0; nt < 4; nt++) {
        int cn = wn * 32 + nt * 8 + g;
        bh[nt][0] = Bh[tig * 72 + cn];
        bh[nt][1] = Bh[(tig + 4) * 72 + cn];
        bl[nt][0] = Bl[tig * 72 + cn];
        bl[nt][1] = Bl[(tig + 4) * 72 + cn];
    }
    #pragma unroll
    for (int mt = 0; mt < 2; mt++) {
        int rm = wm * 32 + mt * 16;
        uint32_t off = (uint32_t)((rm + (lane & 15)) * 48 + (lane >> 4) * 16);
        uint32_t ah[4], al[4];
        ldsm4(ah, a_hi + off);
        ldsm4(al, a_lo + off);
        #pragma unroll
        for (int nt = 0; nt < 4; nt++) {
            mma16(acc[mt][nt], ah, bh[nt]);
            mma16(acc[mt][nt], ah, bl[nt]);
            mma16(acc[mt][nt], al, bh[nt]);
        }
    }
}

// ---------------- bf16x3 MMA GEMM: zconv (128x64 tile, 3-stage, ldsm A) ----------------
__global__ __launch_bounds__(256, 2) void zconv_mma(
    const float* __restrict__ convb, const int* __restrict__ pos)
{
    extern __shared__ __align__(16) char sm[];
    int t = threadIdx.x;
    int w = t >> 5, lane = t & 31, g = lane >> 2, tig = lane & 3;
    int wm = w & 3, wn = w >> 2;
    int n0 = blockIdx.x * 64;
    int by = blockIdx.y;
    int b = by >> 5;
    int s0 = (by & 31) * 128;
    float acc[2][4][4] = {};

    auto issue = [&](int slab, int stage) {
        char* sbase = sm + stage * STG;
        int k0 = slab * 16;
        int tap = k0 >> 8, dbase = k0 & 255;
        #pragma unroll
        for (int p = 0; p < 2; p++) {
            int idx = t + p * 256;
            int arr = idx >> 8, rem = idx & 255;
            int r = rem >> 1, chunk = rem & 1;
            int sp = s0 + r + tap - 1;
            int ok = (sp >= 0 && sp < SS);
            int spc = min(max(sp, 0), SS - 1);
            const __nv_bfloat16* src = (arr ? g_embl : g_embh)
                + (size_t)(b * SS + spc) * 256 + dbase + chunk * 8;
            cpa16(sptr(sbase + arr * 6144 + r * 48 + chunk * 16), src, ok ? 16 : 0);
        }
        {
            int row = t >> 5;
            int arr = (t >> 4) & 1, chunk = t & 15;
            const uint32_t* src = (arr ? g_Wcl : g_Wch)
                + (size_t)((k0 >> 1) + row) * 768 + n0 + chunk * 4;
            cpa16(sptr(sbase + 12288 + arr * 2304 + row * 288 + chunk * 16), src, 16);
        }
        cpa_commit();
    };

    const int KS = 48;
    issue(0, 0);
    issue(1, 1);
    for (int j = 0; j < KS; j++) {
        if (j == KS - 1) cpa_wait0(); else cpa_wait1();
        __syncthreads();
        compute_slab_bf(sm + (j % 3) * STG, wm, wn, g, tig, lane, acc);
        if (j + 2 < KS) issue(j + 2, (j + 2) % 3);
    }
    __syncthreads();

    // staged epilogue: two 64s x 64c halves through smem scratch
    float (*sc)[65] = reinterpret_cast<float(*)[65]>(sm);
    #pragma unroll
    for (int hs = 0; hs < 2; hs++) {
        if ((wm >> 1) == hs) {
            #pragma unroll
            for (int mt = 0; mt < 2; mt++) {
                int sl = (wm & 1) * 32 + mt * 16 + g;
                #pragma unroll
                for (int nt = 0; nt < 4; nt++) {
                    int cl = wn * 32 + nt * 8 + 2 * tig;
                    sc[cl][sl]         = acc[mt][nt][0];
                    sc[cl + 1][sl]     = acc[mt][nt][1];
                    sc[cl][sl + 8]     = acc[mt][nt][2];
                    sc[cl + 1][sl + 8] = acc[mt][nt][3];
                }
            }
        }
        __syncthreads();
        {
            int cl = t >> 2;
            int sl0 = (t & 3) * 16;
            int c = n0 + cl;
            float bias = __ldg(convb + c);
            size_t ch = (size_t)((b * 3 + (c >> 8)) * 256 + (c & 255)) * SS;
            int sbase = s0 + hs * 64 + sl0;
            #pragma unroll
            for (int e4 = 0; e4 < 4; e4++) {
                int s = sbase + e4 * 4;
                float4 v;
                v.x = (sc[cl][sl0 + e4 * 4 + 0] + bias) * ((pos[b * SS + s + 0] != -1) ? 1.f : 0.f);
                v.y = (sc[cl][sl0 + e4 * 4 + 1] + bias) * ((pos[b * SS + s + 1] != -1) ? 1.f : 0.f);
                v.z = (sc[cl][sl0 + e4 * 4 + 2] + bias) * ((pos[b * SS + s + 2] != -1) ? 1.f : 0.f);
                v.w = (sc[cl][sl0 + e4 * 4 + 3] + bias) * ((pos[b * SS + s + 3] != -1) ? 1.f : 0.f);
                *(float4*)(g_z + ch + s) = v;
            }
        }
        __syncthreads();
    }
}

// ---------------- bf16x3 MMA GEMM: ffn1/ffn2/out (128x64 tile, 3-stage, ldsm A) ----------------
template<int SEL, int LDN, bool SCALE, bool MASK>
__global__ __launch_bounds__(256, 2) void ffn_mma(
    const float* __restrict__ bias, const float* __restrict__ scale,
    const int* __restrict__ pos, float* __restrict__ Cout)
{
    const __nv_bfloat16* Ahg = (SEL == 2) ? g_vTh : g_th;
    const __nv_bfloat16* Alg = (SEL == 2) ? g_vTl : g_tl;
    const uint32_t* Bhg = (SEL == 0) ? g_W1h : (SEL == 1) ? g_W2h : g_Woh;
    const uint32_t* Blg = (SEL == 0) ? g_W1l : (SEL == 1) ? g_W2l : g_Wol;
    float* C = (SEL == 0) ? g_h1 : (SEL == 1) ? g_hh : Cout;

    extern __shared__ __align__(16) char sm[];
    int t = threadIdx.x;
    int w = t >> 5, lane = t & 31, g = lane >> 2, tig = lane & 3;
    int wm = w & 3, wn = w >> 2;
    int n0 = blockIdx.x * 64;
    int r0 = blockIdx.y * 128;
    float acc[2][4][4] = {};

    auto issue = [&](int slab, int stage) {
        char* sbase = sm + stage * STG;
        int k0 = slab * 16;
        #pragma unroll
        for (int p = 0; p < 2; p++) {
            int idx = t + p * 256;
            int arr = idx >> 8, rem = idx & 255;
            int r = rem >> 1, chunk = rem & 1;
            const __nv_bfloat16* src = (arr ? Alg : Ahg)
                + (size_t)(r0 + r) * 256 + k0 + chunk * 8;
            cpa16(sptr(sbase + arr * 6144 + r * 48 + chunk * 16), src, 16);
        }
        {
            int row = t >> 5;
            int arr = (t >> 4) & 1, chunk = t & 15;
            const uint32_t* src = (arr ? Blg : Bhg)
                + (size_t)((k0 >> 1) + row) * LDN + n0 + chunk * 4;
            cpa16(sptr(sbase + 12288 + arr * 2304 + row * 288 + chunk * 16), src, 16);
        }
        cpa_commit();
    };

    const int KS = 16;
    issue(0, 0);
    issue(1, 1);
    for (int j = 0; j < KS; j++) {
        if (j == KS - 1) cpa_wait0(); else cpa_wait1();
        __syncthreads();
        compute_slab_bf(sm + (j % 3) * STG, wm, wn, g, tig, lane, acc);
        if (j + 2 < KS) issue(j + 2, (j + 2) % 3);
    }

    #pragma unroll
    for (int mt = 0; mt < 2; mt++) {
        int ra = r0 + wm * 32 + mt * 16 + g;
        int rb = ra + 8;
        float ma = 1.f, mb = 1.f;
        if (MASK) {
            ma = (pos[ra] != -1) ? 1.f : 0.f;
            mb = (pos[rb] != -1) ? 1.f : 0.f;
        }
        #pragma unroll
        for (int nt = 0; nt < 4; nt++) {
            int cn = n0 + wn * 32 + nt * 8 + 2 * tig;
            float2 bi = *(const float2*)(bias + cn);
            float sx = 1.f, sy = 1.f;
            if (SCALE) {
                float2 sc2 = *(const float2*)(scale + cn);
                sx = sc2.x; sy = sc2.y;
            }
            float2 va, vb;
            va.x = (acc[mt][nt][0] + bi.x) * sx * ma;
            va.y = (acc[mt][nt][1] + bi.y) * sy * ma;
            vb.x = (acc[mt][nt][2] + bi.x) * sx * mb;
            vb.y = (acc[mt][nt][3] + bi.y) * sy * mb;
            *(float2*)(C + (size_t)ra * LDN + cn) = va;
            *(float2*)(C + (size_t)rb * LDN + cn) = vb;
        }
    }
}

// LayerNorm (two-pass) + exact gelu: reads g_h1, writes bf16 split to g_th/g_tl
__global__ void ln_gelu_kernel(const float* __restrict__ lng, const float* __restrict__ lnb) {
    int row = blockIdx.x;
    int t = threadIdx.x;
    float v = g_h1[(size_t)row * 256 + t];
    __shared__ float ws[8];
    float s1 = v;
    for (int o = 16; o > 0; o >>= 1) s1 += __shfl_down_sync(0xffffffffu, s1, o);
    if ((t & 31) == 0) ws[t >> 5] = s1;
    __syncthreads();
    if (t == 0) {
        float a = 0.f;
        for (int i = 0; i < 8; i++) a += ws[i];
        ws[0] = a;
    }
    __syncthreads();
    float mu = ws[0] * (1.f / 256.f);
    __syncthreads();
    float dv = v - mu;
    float s2 = dv * dv;
    for (int o = 16; o > 0; o >>= 1) s2 += __shfl_down_sync(0xffffffffu, s2, o);
    if ((t & 31) == 0) ws[t >> 5] = s2;
    __syncthreads();
    if (t == 0) {
        float a = 0.f;
        for (int i = 0; i < 8; i++) a += ws[i];
        ws[0] = a;
    }
    __syncthreads();
    float var = ws[0] * (1.f / 256.f);
    float xn = dv / sqrtf(var + 1e-5f) * lng[t] + lnb[t];
    float ge = 0.5f * xn * (1.f + erff(xn / sqrtf(2.0f)));
    __nv_bfloat16 h = __float2bfloat16(ge);
    g_th[(size_t)row * 256 + t] = h;
    g_tl[(size_t)row * 256 + t] = __float2bfloat16(ge - __bfloat162float(h));
}

// fused L1-normalize + transpose: reads hh once, writes g_h[n][b][d][s]
__global__ void hnorm_kernel() {
    extern __shared__ float hhs[];           // [32][517]
    __shared__ float den[2][32];
    int t = threadIdx.x;
    int b = blockIdx.y;
    int s0 = blockIdx.x * 32;
    #pragma unroll
    for (int j = 0; j < 16; j++) {
        int idx4 = j * 256 + t;
        int s = idx4 >> 7, c4 = idx4 & 127;
        float4 v = *(const float4*)(g_hh + ((size_t)(b * SS + s0 + s)) * 512 + c4 * 4);
        float* dst = &hhs[s * 517 + c4 * 4];
        dst[0] = v.x; dst[1] = v.y; dst[2] = v.z; dst[3] = v.w;
    }
    __syncthreads();
    {
        int w = t >> 5, lane = t & 31;
        #pragma unroll
        for (int rr = 0; rr < 4; rr++) {
            int s = w + rr * 8;
            #pragma unroll
            for (int n = 0; n < 2; n++) {
                float a = 0.f;
                #pragma unroll
                for (int k = 0; k < 8; k++)
                    a += fabsf(hhs[s * 517 + n * 256 + lane + k * 32]);
                for (int o = 16; o > 0; o >>= 1) a += __shfl_down_sync(0xffffffffu, a, o);
                if (lane == 0) den[n][s] = a + 1e-8f;
            }
        }
    }
    __syncthreads();
    #pragma unroll
    for (int wv = 0; wv < 64; wv++) {
        int linear = wv * 256 + t;
        int sl = linear & 31;
        int col = linear >> 5;
        int n = col >> 8, d = col & 255;
        float v = hhs[sl * 517 + col] / den[n][sl];
        g_h[((size_t)(n * BB + b) * 256 + d) * SS + s0 + sl] = v;
    }
}

// ---------------- fused FFT causal conv, radix-2^3 passes ----------------
__global__ __launch_bounds__(1024, 1) void fftconv_fused() {
    extern __shared__ float2 smbuf[];
    float2* sa = smbuf;
    float2* sb = smbuf + SA_PAD;
    float2* tw = smbuf + 2 * SA_PAD;
    int t = threadIdx.x;
    int pi = blockIdx.x;
    int b = pi >> 7;
    int d0 = (pi & 127) * 2;
    const float* xp0 = g_z + (size_t)((b * 3 + 2) * 256 + d0) * SS;
    float* op = g_v + (size_t)(b * 256 + d0) * SS;
    const float R8 = 0.70710678118654752f;

    for (int i = t; i < NF / 4; i += 1024) tw[FIDX(i)] = g_tw[i];
    for (int s = t; s < SS; s += 1024) sa[FIDX(s)] = make_float2(xp0[s], xp0[SS + s]);
    for (int s = SS + t; s < NF; s += 1024) sa[FIDX(s)] = make_float2(0.f, 0.f);

    #pragma unroll 1
    for (int iter = 0; iter < 2; iter++) {
        const float* fp = g_h + (size_t)iter * (BB * DD * SS) + (size_t)(b * 256 + d0) * SS;
        const float* zp = g_z + (size_t)((b * 3 + iter) * 256 + d0) * SS;
        for (int s = t; s < SS; s += 1024) sb[FIDX(s)] = make_float2(fp[s], fp[SS + s]);
        for (int s = SS + t; s < NF; s += 1024) sb[FIDX(s)] = make_float2(0.f, 0.f);
        __syncthreads();

        // forward: 4 radix-2^3 passes (stage triples, sizes 8q/4q/2q), q = 2^lg
        #pragma unroll 1
        for (int lg = 10; lg >= 1; lg -= 3) {
            int q = 1 << lg;
            int s_ = 1 << (10 - lg);           // NF/(8q)
            int j0 = t & (q - 1);
            int p0 = ((t >> lg) << (lg + 3)) + j0;
            float2 w1 = tw[FIDX(j0 * s_)];
            float2 w2 = cmul(w1, w1);
            float2 w4 = cmul(w2, w2);
            float2 w2i = make_float2(w2.y, -w2.x);        // w2 * (-i)
            float2 c8 = make_float2(R8, -R8);
            float2 W1e[4];
            W1e[0] = w1;
            W1e[1] = cmul(w1, c8);
            W1e[2] = make_float2(w1.y, -w1.x);            // w1 * (-i)
            W1e[3] = cmul(W1e[2], c8);
            int idx[8];
            #pragma unroll
            for (int e = 0; e < 8; e++) idx[e] = FIDX(p0 + e * q);
            r8_fwd(sa, idx, W1e, w2, w2i, w4);
            r8_fwd(sb, idx, W1e, w2, w2i, w4);
            __syncthreads();
        }
        // final forward radix-2 stage (half=1, w=1)
        for (int i = t; i < NF / 2; i += 1024) {
            int p0 = FIDX(2 * i), p1 = FIDX(2 * i + 1);
            float2 a = sa[p0], bq = sa[p1];
            sa[p0] = cadd(a, bq); sa[p1] = csub(a, bq);
            float2 c = sb[p0], dq = sb[p1];
            sb[p0] = cadd(c, dq); sb[p1] = csub(c, dq);
        }
        __syncthreads();

        // per-channel spectral product in bit-reversed domain, result packed into sa
        for (int k = t; k < NF / 2; k += 1024) {
            if (k == 0) {
                float2 A0 = sa[0], B0 = sb[0];
                sa[0] = make_float2(A0.x * B0.x, A0.y * B0.y);
                float2 A1 = sa[1], B1 = sb[1];
                sa[1] = make_float2(A1.x * B1.x, A1.y * B1.y);
            } else {
                int p = FIDX(__brev((unsigned)k) >> (32 - LOG2NF));
                int q = FIDX(__brev((unsigned)(NF - k)) >> (32 - LOG2NF));
                float2 A = sa[p], Ac = sa[q];
                float2 Bv = sb[p], Bc = sb[q];
                float Xr  = 0.5f * (A.x + Ac.x),  Xi  = 0.5f * (A.y - Ac.y);
                float Xpr = 0.5f * (A.y + Ac.y),  Xpi = 0.5f * (Ac.x - A.x);
                float Fr  = 0.5f * (Bv.x + Bc.x), Fi  = 0.5f * (Bv.y - Bc.y);
                float Fpr = 0.5f * (Bv.y + Bc.y), Fpi = 0.5f * (Bc.x - Bv.x);
                float Yr  = Xr * Fr - Xi * Fi,     Yi  = Xr * Fi + Xi * Fr;
                float Ypr = Xpr * Fpr - Xpi * Fpi, Ypi = Xpr * Fpi + Xpi * Fpr;
                sa[p] = make_float2(Yr - Ypi, Yi + Ypr);
                sa[q] = make_float2(Yr + Ypi, Ypr - Yi);
            }
        }
        __syncthreads();

        // inverse: first radix-2 stage (m=2, w=1)
        for (int i = t; i < NF / 2; i += 1024) {
            int p0 = FIDX(2 * i), p1 = FIDX(2 * i + 1);
            float2 a = sa[p0], bq = sa[p1];
            sa[p0] = cadd(a, bq); sa[p1] = csub(a, bq);
        }
        __syncthreads();
        // 4 radix-2^3 DIT passes: stage triples (m, 2m, 4m), m = 2^lgm
        #pragma unroll 1
        for (int lgm = 2; lgm <= 11; lgm += 3) {
            int h1 = 1 << (lgm - 1);
            int step = NF >> (lgm + 2);
            int j0 = t & (h1 - 1);
            int p0 = ((t >> (lgm - 1)) << (lgm + 2)) + j0;
            float2 wa = tw[FIDX(j0 * step)];
            float2 w2 = cmul(wa, wa);
            float2 w4 = cmul(w2, w2);
            float2 w2i = make_float2(w2.y, -w2.x);        // w2 * (-i)
            float2 c8 = make_float2(R8, -R8);
            float2 W4e[4];
            W4e[0] = wa;
            W4e[1] = cmul(wa, c8);
            W4e[2] = make_float2(wa.y, -wa.x);            // wa * (-i)
            W4e[3] = cmul(W4e[2], c8);
            int idx[8];
            #pragma unroll
            for (int e = 0; e < 8; e++) idx[e] = FIDX(p0 + e * h1);
            float2 a[8];
            #pragma unroll
            for (int e = 0; e < 8; e++) a[e] = sa[idx[e]];
            float2 bb[8];
            #pragma unroll
            for (int e = 0; e < 8; e += 2) {
                float2 t_ = cmulc(a[e + 1], w4);
                bb[e]     = cadd(a[e], t_);
                bb[e + 1] = csub(a[e], t_);
            }
            float2 cc[8];
            #pragma unroll
            for (int h = 0; h < 8; h += 4) {
                float2 t0 = cmulc(bb[h + 2], w2);
                cc[h]     = cadd(bb[h], t0);
                cc[h + 2] = csub(bb[h], t0);
                float2 t1 = cmulc(bb[h + 3], w2i);
                cc[h + 1] = cadd(bb[h + 1], t1);
                cc[h + 3] = csub(bb[h + 1], t1);
            }
            #pragma unroll
            for (int e = 0; e < 4; e++) {
                float2 t_ = cmulc(cc[e + 4], W4e[e]);
                sa[idx[e]]     = cadd(cc[e], t_);
                sa[idx[e + 4]] = csub(cc[e], t_);
            }
            __syncthreads();
        }

        const float scale = 1.0f / (8192.0f * 8192.0f);
        if (iter == 0) {
            for (int s = t; s < SS; s += 1024) {
                float2 r = sa[FIDX(s)];
                sa[FIDX(s)] = make_float2(zp[s] * (r.x * scale), zp[SS + s] * (r.y * scale));
            }
            for (int s = SS + t; s < NF; s += 1024) sa[FIDX(s)] = make_float2(0.f, 0.f);
        } else {
            for (int s = t; s < SS; s += 1024) {
                float2 r = sa[FIDX(s)];
                op[s]      = zp[s]      * (r.x * scale);
                op[SS + s] = zp[SS + s] * (r.y * scale);
            }
        }
    }
}

// transpose v[b][d][s] -> vT split (bf16 hi/lo) [b*SS+s][d]
__global__ void vtrans_kernel() {
    __shared__ float tile[32][33];
    int tx = threadIdx.x & 31, ty = threadIdx.x >> 5;
    int s0 = blockIdx.x * 32;
    int d0 = blockIdx.y * 32;
    int b = blockIdx.z;
    #pragma unroll
    for (int r = 0; r < 4; r++) {
        int d = d0 + ty + r * 8;
        tile[ty + r * 8][tx] = g_v[(size_t)(b * 256 + d) * SS + s0 + tx];
    }
    __syncthreads();
    #pragma unroll
    for (int r = 0; r < 4; r++) {
        int s = s0 + ty + r * 8;
        float v = tile[tx][ty + r * 8];
        __nv_bfloat16 h = __float2bfloat16(v);
        size_t o = (size_t)(b * SS + s) * 256 + d0 + tx;
        g_vTh[o] = h;
        g_vTl[o] = __float2bfloat16(v - __bfloat162float(h));
    }
}

// ---------------- launch (two-stream fork/join: FFN chain overlaps zconv) ----------------
extern "C" void kernel_launch(void* const* d_in, const int* in_sizes, int n_in,
                              void* d_out, int out_size) {
    const float* emb   = (const float*)d_in[0];
    const int*   pos   = (const int*)d_in[1];
    const float* Wproj = (const float*)d_in[2];
    const float* convw = (const float*)d_in[3];
    const float* convb = (const float*)d_in[4];
    const float* W1    = (const float*)d_in[5];
    const float* b1    = (const float*)d_in[6];
    const float* lng   = (const float*)d_in[7];
    const float* lnb   = (const float*)d_in[8];
    const float* W2    = (const float*)d_in[9];
    const float* b2    = (const float*)d_in[10];
    const float* ffs   = (const float*)d_in[11];
    const float* Wout  = (const float*)d_in[12];
    const float* bout  = (const float*)d_in[13];
    float* out = (float*)d_out;

    static cudaStream_t s2 = nullptr;
    static cudaEvent_t evRoot = nullptr, evFFN = nullptr;
    if (s2 == nullptr) {
        cudaStreamCreateWithFlags(&s2, cudaStreamNonBlocking);
        cudaEventCreateWithFlags(&evRoot, cudaEventDisableTiming);
        cudaEventCreateWithFlags(&evFFN, cudaEventDisableTiming);

        const int fft_smem_i = (2 * SA_PAD + TW_PAD) * 8;
        cudaFuncSetAttribute(fftconv_fused, cudaFuncAttributeMaxDynamicSharedMemorySize, fft_smem_i);
        const int hn_smem_i = 32 * 517 * 4;
        cudaFuncSetAttribute(hnorm_kernel, cudaFuncAttributeMaxDynamicSharedMemorySize, hn_smem_i);
        cudaFuncSetAttribute(zconv_mma, cudaFuncAttributeMaxDynamicSharedMemorySize, GEMM_SMEM);
        cudaFuncSetAttribute((const void*)ffn_mma<0, 256, false, false>, cudaFuncAttributeMaxDynamicSharedMemorySize, GEMM_SMEM);
        cudaFuncSetAttribute((const void*)ffn_mma<1, 512, true, false>, cudaFuncAttributeMaxDynamicSharedMemorySize, GEMM_SMEM);
        cudaFuncSetAttribute((const void*)ffn_mma<2, 256, false, true>, cudaFuncAttributeMaxDynamicSharedMemorySize, GEMM_SMEM);
    }
    const int fft_smem = (2 * SA_PAD + TW_PAD) * 8;
    const int hn_smem = 32 * 517 * 4;

    // fork: s2 joins the capture via evRoot
    cudaEventRecord(evRoot, 0);
    cudaStreamWaitEvent(s2, evRoot, 0);

    // s2: FFN branch (independent of zconv until fftconv)
    tw_init_kernel<<<8, 256, 0, s2>>>();
    minpos_kernel<<<BB, 256, 0, s2>>>(pos);
    wsplit_kernel<<<512, 256, 0, s2>>>(W1, W2, Wout);
    rope_kernel<<<BB * SS, 128, 0, s2>>>(emb, pos);
    ffn_mma<0, 256, false, false><<<dim3(4, 256), 256, GEMM_SMEM, s2>>>(b1, nullptr, nullptr, nullptr);
    ln_gelu_kernel<<<BB * SS, 256, 0, s2>>>(lng, lnb);
    ffn_mma<1, 512, true, false><<<dim3(8, 256), 256, GEMM_SMEM, s2>>>(b2, ffs, nullptr, nullptr);
    hnorm_kernel<<<dim3(SS / 32, BB), 256, hn_smem, s2>>>();
    cudaEventRecord(evFFN, s2);

    // default stream: zconv branch
    emb_split_kernel<<<BB * SS * 256 / 256, 256>>>(emb);
    wc_gemm<<<dim3(12, 4, 3), 256>>>(Wproj, convw);
    zconv_mma<<<dim3(12, 256), 256, GEMM_SMEM>>>(convb, pos);

    // join, then the dependent tail
    cudaStreamWaitEvent(0, evFFN, 0);
    fftconv_fused<<<BB * DD / 2, 1024, fft_smem>>>();
    vtrans_kernel<<<dim3(128, 8, 8), 256>>>();
    ffn_mma<2, 256, false, true><<<dim3(4, 256), 256, GEMM_SMEM>>>(bout, nullptr, pos, out);
}

// round 17
// speedup vs baseline: 1.4238x; 1.4238x over previous
#include <cuda_runtime.h>
#include <cuda_bf16.h>
#include <math.h>
#include <stdint.h>

// Problem constants
#define BB 8
#define SS 4096
#define DD 256
#define GG 3
#define NORD 2
#define NF 8192          // FFT length = 2*S
#define LOG2NF 13

// padded smem index for FFT
#define FIDX(i) ((i) + ((i) >> 4))
#define SA_PAD 8704
#define TW_PAD 2176

// GEMM stage layout (dynamic smem), per stage 16896 B:
//   Ah [128][24] bf16 @ +0      (6144)
//   Al [128][24] bf16 @ +6144   (6144)
//   Bh [8][72]  u32  @ +12288   (2304)
//   Bl [8][72]  u32  @ +14592   (2304)
#define STG 16896
#define GEMM_SMEM (3 * STG)      // 50688

// ---------------- device scratch (static, no allocation) ----------------
__device__ float  g_minpos[BB];
__device__ float  g_theta[128];
__device__ float2 g_tw[NF/4];
__device__ __nv_bfloat16 g_embh[BB * SS * 256];
__device__ __nv_bfloat16 g_embl[BB * SS * 256];
__device__ __nv_bfloat16 g_th[BB * SS * 256];
__device__ __nv_bfloat16 g_tl[BB * SS * 256];
__device__ __nv_bfloat16 g_vTh[BB * SS * 256];
__device__ __nv_bfloat16 g_vTl[BB * SS * 256];
// K-pair-packed bf16 weights: u32 = bf16(k even) | bf16(k odd)<<16, layout [K/2][N]
__device__ uint32_t g_Wch[384 * 768];
__device__ uint32_t g_Wcl[384 * 768];
__device__ uint32_t g_W1h[128 * 256];
__device__ uint32_t g_W1l[128 * 256];
__device__ uint32_t g_W2h[128 * 512];
__device__ uint32_t g_W2l[128 * 512];
__device__ uint32_t g_Woh[128 * 256];
__device__ uint32_t g_Wol[128 * 256];
// f32 intermediates
__device__ float  g_z[BB * GG * DD * SS];          // [b][g][d][s]
__device__ float  g_h1[BB * SS * DD];
__device__ float  g_hh[BB * SS * 2 * DD];
__device__ float  g_h[NORD * BB * DD * SS];        // [n][b][d][s]
__device__ float  g_v[BB * DD * SS];               // [b][d][s]

// ---------------- helpers ----------------
__device__ __forceinline__ uint32_t sptr(const void* p) {
    return (uint32_t)__cvta_generic_to_shared(p);
}
__device__ __forceinline__ void cpa16(uint32_t dst, const void* src, int sz) {
    asm volatile("cp.async.ca.shared.global [%0], [%1], 16, %2;\n"
                 :: "r"(dst), "l"(src), "r"(sz));
}
__device__ __forceinline__ void cpa_commit() {
    asm volatile("cp.async.commit_group;\n" ::: "memory");
}
__device__ __forceinline__ void cpa_wait1() {
    asm volatile("cp.async.wait_group 1;\n" ::: "memory");
}
__device__ __forceinline__ void cpa_wait0() {
    asm volatile("cp.async.wait_group 0;\n" ::: "memory");
}
__device__ __forceinline__ uint32_t pk2(__nv_bfloat16 a, __nv_bfloat16 b) {
    return (uint32_t)__bfloat16_as_ushort(a) | ((uint32_t)__bfloat16_as_ushort(b) << 16);
}
__device__ __forceinline__ void mma16(float c[4], const uint32_t a[4], const uint32_t b[2]) {
    asm volatile(
        "mma.sync.aligned.m16n8k16.row.col.f32.bf16.bf16.f32 "
        "{%0,%1,%2,%3}, {%4,%5,%6,%7}, {%8,%9}, {%0,%1,%2,%3};\n"
        : "+f"(c[0]), "+f"(c[1]), "+f"(c[2]), "+f"(c[3])
        : "r"(a[0]), "r"(a[1]), "r"(a[2]), "r"(a[3]), "r"(b[0]), "r"(b[1]));
}
__device__ __forceinline__ void ldsm4(uint32_t r[4], uint32_t addr) {
    asm volatile("ldmatrix.sync.aligned.m8n8.x4.shared.b16 {%0,%1,%2,%3}, [%4];"
                 : "=r"(r[0]), "=r"(r[1]), "=r"(r[2]), "=r"(r[3]) : "r"(addr));
}
__device__ __forceinline__ float2 cmul(float2 a, float2 b) {
    return make_float2(a.x * b.x - a.y * b.y, a.x * b.y + a.y * b.x);
}
__device__ __forceinline__ float2 cmulc(float2 a, float2 w) {
    return make_float2(a.x * w.x + a.y * w.y, a.y * w.x - a.x * w.y);
}
__device__ __forceinline__ float2 cadd(float2 a, float2 b) { return make_float2(a.x + b.x, a.y + b.y); }
__device__ __forceinline__ float2 csub(float2 a, float2 b) { return make_float2(a.x - b.x, a.y - b.y); }

// One BK=16 slab, warp tile 32x32, bf16x3 (hi*hi + hi*lo + lo*hi)
// A fragments via ldmatrix.x4 (lane l: row rm+(l&15), k-chunk (l>>4)*16B)
__device__ __forceinline__ void compute_slab_bf(
    char* sb, int wm, int wn, int g, int tig, int lane, float acc[2][4][4])
{
    uint32_t a_hi = sptr(sb);
    uint32_t a_lo = a_hi + 6144;
    const uint32_t* Bh = (const uint32_t*)(sb + 12288);
    const uint32_t* Bl = (const uint32_t*)(sb + 14592);

    uint32_t bh[4][2], bl[4][2];
    #pragma unroll
    for (int nt = 0; nt < 4; nt++) {
        int cn = wn * 32 + nt * 8 + g;
        bh[nt][0] = Bh[tig * 72 + cn];
        bh[nt][1] = Bh[(tig + 4) * 72 + cn];
        bl[nt][0] = Bl[tig * 72 + cn];
        bl[nt][1] = Bl[(tig + 4) * 72 + cn];
    }
    #pragma unroll
    for (int mt = 0; mt < 2; mt++) {
        int rm = wm * 32 + mt * 16;
        uint32_t off = (uint32_t)((rm + (lane & 15)) * 48 + (lane >> 4) * 16);
        uint32_t ah[4], al[4];
        ldsm4(ah, a_hi + off);
        ldsm4(al, a_lo + off);
        #pragma unroll
        for (int nt = 0; nt < 4; nt++) {
            mma16(acc[mt][nt], ah, bh[nt]);
            mma16(acc[mt][nt], ah, bl[nt]);
            mma16(acc[mt][nt], al, bh[nt]);
        }
    }
}

// ---------------- split precompute kernels ----------------
__global__ void emb_split_kernel(const float* __restrict__ emb) {
    int i = blockIdx.x * 256 + threadIdx.x;
    float v = emb[i];
    __nv_bfloat16 h = __float2bfloat16(v);
    g_embh[i] = h;
    g_embl[i] = __float2bfloat16(v - __bfloat162float(h));
}

__global__ void wsplit_kernel(const float* __restrict__ W1, const float* __restrict__ W2,
                              const float* __restrict__ Wout) {
    int idx = blockIdx.x * 256 + threadIdx.x;
    const float* src; uint32_t *dh, *dl; int LDN, loc;
    if (idx < 32768)       { src = W1;   dh = g_W1h; dl = g_W1l; LDN = 256; loc = idx; }
    else if (idx < 98304)  { src = W2;   dh = g_W2h; dl = g_W2l; LDN = 512; loc = idx - 32768; }
    else                   { src = Wout; dh = g_Woh; dl = g_Wol; LDN = 256; loc = idx - 98304; }
    int kp = loc / LDN, n = loc % LDN;
    float v0 = src[(size_t)(2 * kp) * LDN + n];
    float v1 = src[(size_t)(2 * kp + 1) * LDN + n];
    __nv_bfloat16 h0 = __float2bfloat16(v0), h1 = __float2bfloat16(v1);
    dh[loc] = pk2(h0, h1);
    dl[loc] = pk2(__float2bfloat16(v0 - __bfloat162float(h0)),
                  __float2bfloat16(v1 - __bfloat162float(h1)));
}

// ---------------- init kernels ----------------
__global__ void tw_init_kernel() {
    int k = blockIdx.x * blockDim.x + threadIdx.x;
    if (k < NF/4) {
        double a = -2.0 * 3.14159265358979323846 * (double)k / (double)NF;
        double s, c;
        sincos(a, &s, &c);
        g_tw[k] = make_float2((float)c, (float)s);
    }
    if (k < 128) {
        float frac = (float)k * (1.0f / 128.0f);
        g_theta[k] = 1.0f / powf(10000.0f, frac);
    }
}

__global__ void minpos_kernel(const int* __restrict__ pos) {
    int b = blockIdx.x;
    int t = threadIdx.x;
    int local = 0x7fffffff;
    for (int s = t; s < SS; s += blockDim.x) {
        int p = pos[b * SS + s];
        if (p != -1) local = min(local, p);
    }
    for (int o = 16; o > 0; o >>= 1) local = min(local, __shfl_down_sync(0xffffffffu, local, o));
    __shared__ int wmin[8];
    if ((t & 31) == 0) wmin[t >> 5] = local;
    __syncthreads();
    if (t == 0) {
        int m = wmin[0];
        for (int i = 1; i < (int)(blockDim.x >> 5); i++) m = min(m, wmin[i]);
        g_minpos[b] = (float)m;
    }
}

// ---------------- SIMT gemm for Wc precompute ----------------
#define GEMM_CORE()                                                        \
    __syncthreads();                                                       \
    _Pragma("unroll")                                                      \
    for (int kk = 0; kk < 16; kk++) {                                      \
        float4 af = *(const float4*)&As[kk][ty * 4];                       \
        float4 bf = *(const float4*)&Bs[kk][tx * 4];                       \
        float ar[4] = {af.x, af.y, af.z, af.w};                            \
        float br[4] = {bf.x, bf.y, bf.z, bf.w};                            \
        _Pragma("unroll")                                                  \
        for (int i = 0; i < 4; i++)                                        \
            _Pragma("unroll")                                              \
            for (int j = 0; j < 4; j++) acc[i][j] += ar[i] * br[j];        \
    }                                                                      \
    __syncthreads();

__global__ void wc_gemm(const float* __restrict__ Wproj, const float* __restrict__ convw) {
    __shared__ __align__(16) float As[16][64];
    __shared__ __align__(16) float Bs[16][64];
    int t = threadIdx.x;
    int tx = t & 15, ty = t >> 4;
    int n0 = blockIdx.x * 64;         // c
    int m0 = blockIdx.y * 64;         // d
    int tap = blockIdx.z;
    int g = n0 >> 8;
    int am = t >> 2, akq = t & 3;
    int bk = t >> 4, bnq = t & 15;
    float acc[4][4] = {};
    for (int k0 = 0; k0 < 256; k0 += 16) {
        float4 av = *(const float4*)(Wproj + (size_t)(m0 + am) * 768 + g * 256 + k0 + akq * 4);
        As[akq * 4 + 0][am] = av.x;
        As[akq * 4 + 1][am] = av.y;
        As[akq * 4 + 2][am] = av.z;
        As[akq * 4 + 3][am] = av.w;
        int i = k0 + bk;
        int c = n0 + bnq * 4;
        #pragma unroll
        for (int e = 0; e < 4; e++)
            Bs[bk][bnq * 4 + e] = convw[(size_t)(c + e) * 768 + i * 3 + tap];
        GEMM_CORE()
    }
    #pragma unroll
    for (int i = 0; i < 4; i += 2) {
        int kglob = tap * 256 + m0 + ty * 4 + i;
        size_t kpg = (size_t)(kglob >> 1);
        #pragma unroll
        for (int j = 0; j < 4; j++) {
            float v0 = acc[i][j], v1 = acc[i + 1][j];
            __nv_bfloat16 h0 = __float2bfloat16(v0), h1 = __float2bfloat16(v1);
            int cidx = n0 + tx * 4 + j;
            g_Wch[kpg * 768 + cidx] = pk2(h0, h1);
            g_Wcl[kpg * 768 + cidx] = pk2(__float2bfloat16(v0 - __bfloat162float(h0)),
                                          __float2bfloat16(v1 - __bfloat162float(h1)));
        }
    }
}

// ---------------- rope (writes bf16 split) ----------------
__global__ void rope_kernel(const float* __restrict__ emb, const int* __restrict__ pos) {
    int row = blockIdx.x;
    int i = threadIdx.x;
    int b = row >> 12;
    float2 xv = *(const float2*)(emb + (size_t)row * 256 + 2 * i);
    float theta = g_theta[i];
    int p = pos[row];
    float adj = (p == -1) ? -1.0f : ((float)p - g_minpos[b]);
    float ang = adj * theta;
    float sn, cs;
    sincosf(ang, &sn, &cs);
    float rx = xv.x * cs - xv.y * sn;
    float ry = xv.x * sn + xv.y * cs;
    __nv_bfloat16 hx = __float2bfloat16(rx), hy = __float2bfloat16(ry);
    size_t o = (size_t)row * 256 + 2 * i;
    *(uint32_t*)(g_th + o) = pk2(hx, hy);
    *(uint32_t*)(g_tl + o) = pk2(__float2bfloat16(rx - __bfloat162float(hx)),
                                 __float2bfloat16(ry - __bfloat162float(hy)));
}

// ---------------- bf16x3 MMA GEMM: zconv (128x64 tile, 3-stage, ldsm A) ----------------
__global__ __launch_bounds__(256, 2) void zconv_mma(
    const float* __restrict__ convb, const int* __restrict__ pos)
{
    extern __shared__ __align__(16) char sm[];
    int t = threadIdx.x;
    int w = t >> 5, lane = t & 31, g = lane >> 2, tig = lane & 3;
    int wm = w & 3, wn = w >> 2;
    int n0 = blockIdx.x * 64;
    int by = blockIdx.y;
    int b = by >> 5;
    int s0 = (by & 31) * 128;
    float acc[2][4][4] = {};

    auto issue = [&](int slab, int stage) {
        char* sbase = sm + stage * STG;
        int k0 = slab * 16;
        int tap = k0 >> 8, dbase = k0 & 255;
        #pragma unroll
        for (int p = 0; p < 2; p++) {
            int idx = t + p * 256;
            int arr = idx >> 8, rem = idx & 255;
            int r = rem >> 1, chunk = rem & 1;
            int sp = s0 + r + tap - 1;
            int ok = (sp >= 0 && sp < SS);
            int spc = min(max(sp, 0), SS - 1);
            const __nv_bfloat16* src = (arr ? g_embl : g_embh)
                + (size_t)(b * SS + spc) * 256 + dbase + chunk * 8;
            cpa16(sptr(sbase + arr * 6144 + r * 48 + chunk * 16), src, ok ? 16 : 0);
        }
        {
            int row = t >> 5;
            int arr = (t >> 4) & 1, chunk = t & 15;
            const uint32_t* src = (arr ? g_Wcl : g_Wch)
                + (size_t)((k0 >> 1) + row) * 768 + n0 + chunk * 4;
            cpa16(sptr(sbase + 12288 + arr * 2304 + row * 288 + chunk * 16), src, 16);
        }
        cpa_commit();
    };

    const int KS = 48;
    issue(0, 0);
    issue(1, 1);
    for (int j = 0; j < KS; j++) {
        if (j == KS - 1) cpa_wait0(); else cpa_wait1();
        __syncthreads();
        compute_slab_bf(sm + (j % 3) * STG, wm, wn, g, tig, lane, acc);
        if (j + 2 < KS) issue(j + 2, (j + 2) % 3);
    }
    __syncthreads();

    // staged epilogue: two 64s x 64c halves through smem scratch
    float (*sc)[65] = reinterpret_cast<float(*)[65]>(sm);
    #pragma unroll
    for (int hs = 0; hs < 2; hs++) {
        if ((wm >> 1) == hs) {
            #pragma unroll
            for (int mt = 0; mt < 2; mt++) {
                int sl = (wm & 1) * 32 + mt * 16 + g;
                #pragma unroll
                for (int nt = 0; nt < 4; nt++) {
                    int cl = wn * 32 + nt * 8 + 2 * tig;
                    sc[cl][sl]         = acc[mt][nt][0];
                    sc[cl + 1][sl]     = acc[mt][nt][1];
                    sc[cl][sl + 8]     = acc[mt][nt][2];
                    sc[cl + 1][sl + 8] = acc[mt][nt][3];
                }
            }
        }
        __syncthreads();
        {
            int cl = t >> 2;
            int sl0 = (t & 3) * 16;
            int c = n0 + cl;
            float bias = __ldg(convb + c);
            size_t ch = (size_t)((b * 3 + (c >> 8)) * 256 + (c & 255)) * SS;
            int sbase = s0 + hs * 64 + sl0;
            #pragma unroll
            for (int e4 = 0; e4 < 4; e4++) {
                int s = sbase + e4 * 4;
                float4 v;
                v.x = (sc[cl][sl0 + e4 * 4 + 0] + bias) * ((pos[b * SS + s + 0] != -1) ? 1.f : 0.f);
                v.y = (sc[cl][sl0 + e4 * 4 + 1] + bias) * ((pos[b * SS + s + 1] != -1) ? 1.f : 0.f);
                v.z = (sc[cl][sl0 + e4 * 4 + 2] + bias) * ((pos[b * SS + s + 2] != -1) ? 1.f : 0.f);
                v.w = (sc[cl][sl0 + e4 * 4 + 3] + bias) * ((pos[b * SS + s + 3] != -1) ? 1.f : 0.f);
                *(float4*)(g_z + ch + s) = v;
            }
        }
        __syncthreads();
    }
}

// ---------------- bf16x3 MMA GEMM: ffn1/ffn2/out (128x64 tile, 3-stage, ldsm A) ----------------
// SEL=0: A=g_t*,  B=W1, C=g_h1 (LDN=256)
// SEL=1: A=g_t*,  B=W2, C=g_hh (LDN=512, scale)
// SEL=2: A=g_vT*, B=Wo, C=Cout (LDN=256, mask)
template<int SEL, int LDN, bool SCALE, bool MASK>
__global__ __launch_bounds__(256, 2) void ffn_mma(
    const float* __restrict__ bias, const float* __restrict__ scale,
    const int* __restrict__ pos, float* __restrict__ Cout)
{
    const __nv_bfloat16* Ahg = (SEL == 2) ? g_vTh : g_th;
    const __nv_bfloat16* Alg = (SEL == 2) ? g_vTl : g_tl;
    const uint32_t* Bhg = (SEL == 0) ? g_W1h : (SEL == 1) ? g_W2h : g_Woh;
    const uint32_t* Blg = (SEL == 0) ? g_W1l : (SEL == 1) ? g_W2l : g_Wol;
    float* C = (SEL == 0) ? g_h1 : (SEL == 1) ? g_hh : Cout;

    extern __shared__ __align__(16) char sm[];
    int t = threadIdx.x;
    int w = t >> 5, lane = t & 31, g = lane >> 2, tig = lane & 3;
    int wm = w & 3, wn = w >> 2;
    int n0 = blockIdx.x * 64;
    int r0 = blockIdx.y * 128;
    float acc[2][4][4] = {};

    auto issue = [&](int slab, int stage) {
        char* sbase = sm + stage * STG;
        int k0 = slab * 16;
        #pragma unroll
        for (int p = 0; p < 2; p++) {
            int idx = t + p * 256;
            int arr = idx >> 8, rem = idx & 255;
            int r = rem >> 1, chunk = rem & 1;
            const __nv_bfloat16* src = (arr ? Alg : Ahg)
                + (size_t)(r0 + r) * 256 + k0 + chunk * 8;
            cpa16(sptr(sbase + arr * 6144 + r * 48 + chunk * 16), src, 16);
        }
        {
            int row = t >> 5;
            int arr = (t >> 4) & 1, chunk = t & 15;
            const uint32_t* src = (arr ? Blg : Bhg)
                + (size_t)((k0 >> 1) + row) * LDN + n0 + chunk * 4;
            cpa16(sptr(sbase + 12288 + arr * 2304 + row * 288 + chunk * 16), src, 16);
        }
        cpa_commit();
    };

    const int KS = 16;
    issue(0, 0);
    issue(1, 1);
    for (int j = 0; j < KS; j++) {
        if (j == KS - 1) cpa_wait0(); else cpa_wait1();
        __syncthreads();
        compute_slab_bf(sm + (j % 3) * STG, wm, wn, g, tig, lane, acc);
        if (j + 2 < KS) issue(j + 2, (j + 2) % 3);
    }

    #pragma unroll
    for (int mt = 0; mt < 2; mt++) {
        int ra = r0 + wm * 32 + mt * 16 + g;
        int rb = ra + 8;
        float ma = 1.f, mb = 1.f;
        if (MASK) {
            ma = (pos[ra] != -1) ? 1.f : 0.f;
            mb = (pos[rb] != -1) ? 1.f : 0.f;
        }
        #pragma unroll
        for (int nt = 0; nt < 4; nt++) {
            int cn = n0 + wn * 32 + nt * 8 + 2 * tig;
            float2 bi = *(const float2*)(bias + cn);
            float sx = 1.f, sy = 1.f;
            if (SCALE) {
                float2 sc2 = *(const float2*)(scale + cn);
                sx = sc2.x; sy = sc2.y;
            }
            float2 va, vb;
            va.x = (acc[mt][nt][0] + bi.x) * sx * ma;
            va.y = (acc[mt][nt][1] + bi.y) * sy * ma;
            vb.x = (acc[mt][nt][2] + bi.x) * sx * mb;
            vb.y = (acc[mt][nt][3] + bi.y) * sy * mb;
            *(float2*)(C + (size_t)ra * LDN + cn) = va;
            *(float2*)(C + (size_t)rb * LDN + cn) = vb;
        }
    }
}

// LayerNorm (two-pass) + exact gelu: reads g_h1, writes bf16 split to g_th/g_tl
__global__ void ln_gelu_kernel(const float* __restrict__ lng, const float* __restrict__ lnb) {
    int row = blockIdx.x;
    int t = threadIdx.x;
    float v = g_h1[(size_t)row * 256 + t];
    __shared__ float ws[8];
    float s1 = v;
    for (int o = 16; o > 0; o >>= 1) s1 += __shfl_down_sync(0xffffffffu, s1, o);
    if ((t & 31) == 0) ws[t >> 5] = s1;
    __syncthreads();
    if (t == 0) {
        float a = 0.f;
        for (int i = 0; i < 8; i++) a += ws[i];
        ws[0] = a;
    }
    __syncthreads();
    float mu = ws[0] * (1.f / 256.f);
    __syncthreads();
    float dv = v - mu;
    float s2 = dv * dv;
    for (int o = 16; o > 0; o >>= 1) s2 += __shfl_down_sync(0xffffffffu, s2, o);
    if ((t & 31) == 0) ws[t >> 5] = s2;
    __syncthreads();
    if (t == 0) {
        float a = 0.f;
        for (int i = 0; i < 8; i++) a += ws[i];
        ws[0] = a;
    }
    __syncthreads();
    float var = ws[0] * (1.f / 256.f);
    float xn = dv / sqrtf(var + 1e-5f) * lng[t] + lnb[t];
    float ge = 0.5f * xn * (1.f + erff(xn / sqrtf(2.0f)));
    __nv_bfloat16 h = __float2bfloat16(ge);
    g_th[(size_t)row * 256 + t] = h;
    g_tl[(size_t)row * 256 + t] = __float2bfloat16(ge - __bfloat162float(h));
}

// fused L1-normalize + transpose: reads hh once, writes g_h[n][b][d][s]
__global__ void hnorm_kernel() {
    extern __shared__ float hhs[];           // [32][517]
    __shared__ float den[2][32];
    int t = threadIdx.x;
    int b = blockIdx.y;
    int s0 = blockIdx.x * 32;
    #pragma unroll
    for (int j = 0; j < 16; j++) {
        int idx4 = j * 256 + t;
        int s = idx4 >> 7, c4 = idx4 & 127;
        float4 v = *(const float4*)(g_hh + ((size_t)(b * SS + s0 + s)) * 512 + c4 * 4);
        float* dst = &hhs[s * 517 + c4 * 4];
        dst[0] = v.x; dst[1] = v.y; dst[2] = v.z; dst[3] = v.w;
    }
    __syncthreads();
    {
        int w = t >> 5, lane = t & 31;
        #pragma unroll
        for (int rr = 0; rr < 4; rr++) {
            int s = w + rr * 8;
            #pragma unroll
            for (int n = 0; n < 2; n++) {
                float a = 0.f;
                #pragma unroll
                for (int k = 0; k < 8; k++)
                    a += fabsf(hhs[s * 517 + n * 256 + lane + k * 32]);
                for (int o = 16; o > 0; o >>= 1) a += __shfl_down_sync(0xffffffffu, a, o);
                if (lane == 0) den[n][s] = a + 1e-8f;
            }
        }
    }
    __syncthreads();
    #pragma unroll
    for (int wv = 0; wv < 64; wv++) {
        int linear = wv * 256 + t;
        int sl = linear & 31;
        int col = linear >> 5;
        int n = col >> 8, d = col & 255;
        float v = hhs[sl * 517 + col] / den[n][sl];
        g_h[((size_t)(n * BB + b) * 256 + d) * SS + s0 + sl] = v;
    }
}

// ---------------- fused FFT causal conv (radix-2^2, conflict-free FIDX) ----------------
__global__ __launch_bounds__(1024, 1) void fftconv_fused() {
    extern __shared__ float2 smbuf[];
    float2* sa = smbuf;
    float2* sb = smbuf + SA_PAD;
    float2* tw = smbuf + 2 * SA_PAD;
    int t = threadIdx.x;
    int pi = blockIdx.x;
    int b = pi >> 7;
    int d0 = (pi & 127) * 2;
    const float* xp0 = g_z + (size_t)((b * 3 + 2) * 256 + d0) * SS;
    float* op = g_v + (size_t)(b * 256 + d0) * SS;

    for (int i = t; i < NF / 4; i += 1024) tw[FIDX(i)] = g_tw[i];
    for (int s = t; s < SS; s += 1024) sa[FIDX(s)] = make_float2(xp0[s], xp0[SS + s]);
    for (int s = SS + t; s < NF; s += 1024) sa[FIDX(s)] = make_float2(0.f, 0.f);

    #pragma unroll 1
    for (int iter = 0; iter < 2; iter++) {
        const float* fp = g_h + (size_t)iter * (BB * DD * SS) + (size_t)(b * 256 + d0) * SS;
        const float* zp = g_z + (size_t)((b * 3 + iter) * 256 + d0) * SS;
        for (int s = t; s < SS; s += 1024) sb[FIDX(s)] = make_float2(fp[s], fp[SS + s]);
        for (int s = SS + t; s < NF; s += 1024) sb[FIDX(s)] = make_float2(0.f, 0.f);
        __syncthreads();

        #pragma unroll 1
        for (int lg = 11; lg >= 1; lg -= 2) {
            int hh = 1 << lg;
            int H = hh << 1;
            int ts1 = 1 << (11 - lg);
            for (int u = t; u < NF / 4; u += 1024) {
                int j0 = u & (hh - 1);
                int p0 = ((u >> lg) << (lg + 2)) + j0;
                int i0 = FIDX(p0), i1 = FIDX(p0 + hh), i2 = FIDX(p0 + H), i3 = FIDX(p0 + H + hh);
                float2 w1 = tw[FIDX(j0 * ts1)];
                float2 w1b = make_float2(w1.y, -w1.x);
                float2 w2 = cmul(w1, w1);
                {
                    float2 a0 = sa[i0], a1 = sa[i1], a2 = sa[i2], a3 = sa[i3];
                    float2 t0 = cadd(a0, a2), u2 = cmul(csub(a0, a2), w1);
                    float2 t1 = cadd(a1, a3), u3 = cmul(csub(a1, a3), w1b);
                    sa[i0] = cadd(t0, t1);
                    sa[i1] = cmul(csub(t0, t1), w2);
                    sa[i2] = cadd(u2, u3);
                    sa[i3] = cmul(csub(u2, u3), w2);
                }
                {
                    float2 a0 = sb[i0], a1 = sb[i1], a2 = sb[i2], a3 = sb[i3];
                    float2 t0 = cadd(a0, a2), u2 = cmul(csub(a0, a2), w1);
                    float2 t1 = cadd(a1, a3), u3 = cmul(csub(a1, a3), w1b);
                    sb[i0] = cadd(t0, t1);
                    sb[i1] = cmul(csub(t0, t1), w2);
                    sb[i2] = cadd(u2, u3);
                    sb[i3] = cmul(csub(u2, u3), w2);
                }
            }
            __syncthreads();
        }
        for (int i = t; i < NF / 2; i += 1024) {
            int p0 = FIDX(2 * i), p1 = FIDX(2 * i + 1);
            float2 a = sa[p0], bq = sa[p1];
            sa[p0] = cadd(a, bq); sa[p1] = csub(a, bq);
            float2 c = sb[p0], dq = sb[p1];
            sb[p0] = cadd(c, dq); sb[p1] = csub(c, dq);
        }
        __syncthreads();

        for (int k = t; k < NF / 2; k += 1024) {
            if (k == 0) {
                float2 A0 = sa[0], B0 = sb[0];
                sa[0] = make_float2(A0.x * B0.x, A0.y * B0.y);
                float2 A1 = sa[1], B1 = sb[1];
                sa[1] = make_float2(A1.x * B1.x, A1.y * B1.y);
            } else {
                int p = FIDX(__brev((unsigned)k) >> (32 - LOG2NF));
                int q = FIDX(__brev((unsigned)(NF - k)) >> (32 - LOG2NF));
                float2 A = sa[p], Ac = sa[q];
                float2 Bv = sb[p], Bc = sb[q];
                float Xr  = 0.5f * (A.x + Ac.x),  Xi  = 0.5f * (A.y - Ac.y);
                float Xpr = 0.5f * (A.y + Ac.y),  Xpi = 0.5f * (Ac.x - A.x);
                float Fr  = 0.5f * (Bv.x + Bc.x), Fi  = 0.5f * (Bv.y - Bc.y);
                float Fpr = 0.5f * (Bv.y + Bc.y), Fpi = 0.5f * (Bc.x - Bv.x);
                float Yr  = Xr * Fr - Xi * Fi,     Yi  = Xr * Fi + Xi * Fr;
                float Ypr = Xpr * Fpr - Xpi * Fpi, Ypi = Xpr * Fpi + Xpi * Fpr;
                sa[p] = make_float2(Yr - Ypi, Yi + Ypr);
                sa[q] = make_float2(Yr + Ypi, Ypr - Yi);
            }
        }
        __syncthreads();

        for (int i = t; i < NF / 2; i += 1024) {
            int p0 = FIDX(2 * i), p1 = FIDX(2 * i + 1);
            float2 a = sa[p0], bq = sa[p1];
            sa[p0] = cadd(a, bq); sa[p1] = csub(a, bq);
        }
        __syncthreads();
        #pragma unroll 1
        for (int lgm = 2; lgm <= 12; lgm += 2) {
            int m = 1 << lgm;
            int hm = m >> 1;
            int ts = NF >> (lgm + 1);
            for (int u = t; u < NF / 4; u += 1024) {
                int j0 = u & (hm - 1);
                int p0 = ((u >> (lgm - 1)) << (lgm + 1)) + j0;
                int i0 = FIDX(p0), i1 = FIDX(p0 + hm), i2 = FIDX(p0 + m), i3 = FIDX(p0 + m + hm);
                float2 wb = tw[FIDX(j0 * ts)];
                float2 wm = cmul(wb, wb);
                float2 a0 = sa[i0], a1 = sa[i1], a2 = sa[i2], a3 = sa[i3];
                float2 t1 = cmulc(a1, wm);
                float2 o0 = cadd(a0, t1), o1 = csub(a0, t1);
                float2 t3 = cmulc(a3, wm);
                float2 o2 = cadd(a2, t3), o3 = csub(a2, t3);
                float2 c2 = cmulc(o2, wb);
                float2 cz = cmulc(o3, wb);
                float2 t2 = make_float2(-cz.y, cz.x);
                sa[i0] = cadd(o0, c2);
                sa[i2] = csub(o0, c2);
                sa[i1] = cadd(o1, t2);
                sa[i3] = csub(o1, t2);
            }
            __syncthreads();
        }

        const float scale = 1.0f / (8192.0f * 8192.0f);
        if (iter == 0) {
            for (int s = t; s < SS; s += 1024) {
                float2 r = sa[FIDX(s)];
                sa[FIDX(s)] = make_float2(zp[s] * (r.x * scale), zp[SS + s] * (r.y * scale));
            }
            for (int s = SS + t; s < NF; s += 1024) sa[FIDX(s)] = make_float2(0.f, 0.f);
        } else {
            for (int s = t; s < SS; s += 1024) {
                float2 r = sa[FIDX(s)];
                op[s]      = zp[s]      * (r.x * scale);
                op[SS + s] = zp[SS + s] * (r.y * scale);
            }
        }
    }
}

// transpose v[b][d][s] -> vT split (bf16 hi/lo) [b*SS+s][d]
__global__ void vtrans_kernel() {
    __shared__ float tile[32][33];
    int tx = threadIdx.x & 31, ty = threadIdx.x >> 5;
    int s0 = blockIdx.x * 32;
    int d0 = blockIdx.y * 32;
    int b = blockIdx.z;
    #pragma unroll
    for (int r = 0; r < 4; r++) {
        int d = d0 + ty + r * 8;
        tile[ty + r * 8][tx] = g_v[(size_t)(b * 256 + d) * SS + s0 + tx];
    }
    __syncthreads();
    #pragma unroll
    for (int r = 0; r < 4; r++) {
        int s = s0 + ty + r * 8;
        float v = tile[tx][ty + r * 8];
        __nv_bfloat16 h = __float2bfloat16(v);
        size_t o = (size_t)(b * SS + s) * 256 + d0 + tx;
        g_vTh[o] = h;
        g_vTl[o] = __float2bfloat16(v - __bfloat162float(h));
    }
}

// ---------------- launch (two-stream fork/join: FFN chain overlaps zconv) ----------------
extern "C" void kernel_launch(void* const* d_in, const int* in_sizes, int n_in,
                              void* d_out, int out_size) {
    const float* emb   = (const float*)d_in[0];
    const int*   pos   = (const int*)d_in[1];
    const float* Wproj = (const float*)d_in[2];
    const float* convw = (const float*)d_in[3];
    const float* convb = (const float*)d_in[4];
    const float* W1    = (const float*)d_in[5];
    const float* b1    = (const float*)d_in[6];
    const float* lng   = (const float*)d_in[7];
    const float* lnb   = (const float*)d_in[8];
    const float* W2    = (const float*)d_in[9];
    const float* b2    = (const float*)d_in[10];
    const float* ffs   = (const float*)d_in[11];
    const float* Wout  = (const float*)d_in[12];
    const float* bout  = (const float*)d_in[13];
    float* out = (float*)d_out;

    static cudaStream_t s2 = nullptr;
    static cudaEvent_t evRoot = nullptr, evFFN = nullptr;
    if (s2 == nullptr) {
        cudaStreamCreateWithFlags(&s2, cudaStreamNonBlocking);
        cudaEventCreateWithFlags(&evRoot, cudaEventDisableTiming);
        cudaEventCreateWithFlags(&evFFN, cudaEventDisableTiming);

        const int fft_smem_i = (2 * SA_PAD + TW_PAD) * 8;
        cudaFuncSetAttribute(fftconv_fused, cudaFuncAttributeMaxDynamicSharedMemorySize, fft_smem_i);
        const int hn_smem_i = 32 * 517 * 4;
        cudaFuncSetAttribute(hnorm_kernel, cudaFuncAttributeMaxDynamicSharedMemorySize, hn_smem_i);
        cudaFuncSetAttribute(zconv_mma, cudaFuncAttributeMaxDynamicSharedMemorySize, GEMM_SMEM);
        cudaFuncSetAttribute((const void*)ffn_mma<0, 256, false, false>, cudaFuncAttributeMaxDynamicSharedMemorySize, GEMM_SMEM);
        cudaFuncSetAttribute((const void*)ffn_mma<1, 512, true, false>, cudaFuncAttributeMaxDynamicSharedMemorySize, GEMM_SMEM);
        cudaFuncSetAttribute((const void*)ffn_mma<2, 256, false, true>, cudaFuncAttributeMaxDynamicSharedMemorySize, GEMM_SMEM);
    }
    const int fft_smem = (2 * SA_PAD + TW_PAD) * 8;
    const int hn_smem = 32 * 517 * 4;

    // fork: s2 joins the capture via evRoot
    cudaEventRecord(evRoot, 0);
    cudaStreamWaitEvent(s2, evRoot, 0);

    // s2: FFN branch (independent of zconv until fftconv)
    tw_init_kernel<<<8, 256, 0, s2>>>();
    minpos_kernel<<<BB, 256, 0, s2>>>(pos);
    wsplit_kernel<<<512, 256, 0, s2>>>(W1, W2, Wout);
    rope_kernel<<<BB * SS, 128, 0, s2>>>(emb, pos);
    ffn_mma<0, 256, false, false><<<dim3(4, 256), 256, GEMM_SMEM, s2>>>(b1, nullptr, nullptr, nullptr);
    ln_gelu_kernel<<<BB * SS, 256, 0, s2>>>(lng, lnb);
    ffn_mma<1, 512, true, false><<<dim3(8, 256), 256, GEMM_SMEM, s2>>>(b2, ffs, nullptr, nullptr);
    hnorm_kernel<<<dim3(SS / 32, BB), 256, hn_smem, s2>>>();
    cudaEventRecord(evFFN, s2);

    // default stream: zconv branch
    emb_split_kernel<<<BB * SS * 256 / 256, 256>>>(emb);
    wc_gemm<<<dim3(12, 4, 3), 256>>>(Wproj, convw);
    zconv_mma<<<dim3(12, 256), 256, GEMM_SMEM>>>(convb, pos);

    // join, then the dependent tail
    cudaStreamWaitEvent(0, evFFN, 0);
    fftconv_fused<<<BB * DD / 2, 1024, fft_smem>>>();
    vtrans_kernel<<<dim3(128, 8, 8), 256>>>();
    ffn_mma<2, 256, false, true><<<dim3(4, 256), 256, GEMM_SMEM>>>(bout, nullptr, pos, out);
}